// round 1
// baseline (speedup 1.0000x reference)
#include <cuda_runtime.h>
#include <math.h>

#define DM 96
#define DI 192
#define HW 24
#define NPOS 576
#define NB 2

// Scratch (allocation-free rule: __device__ globals)
__device__ float g_xn[NB * DM * NPOS];
__device__ float g_xz[NB * 2 * DI * NPOS];
__device__ float g_mid[NB * DM * NPOS];

// ---------------- rmsnorm over W (last axis, 24 elems) ----------------
__global__ void rms_kernel(const float* __restrict__ src, long cstride, long nstride,
                           const float* __restrict__ nw) {
    int row  = blockIdx.x * 8 + (threadIdx.x >> 5);   // (n,c,h) row id, 4608 total
    int lane = threadIdx.x & 31;
    if (row >= NB * DM * HW) return;
    int h = row % HW;
    int c = (row / HW) % DM;
    int n = row / (HW * DM);
    const float* p = src + (size_t)n * nstride + (size_t)c * cstride + h * HW;
    float v = (lane < HW) ? p[lane] : 0.f;
    float s = v * v;
    #pragma unroll
    for (int o = 16; o; o >>= 1) s += __shfl_xor_sync(0xffffffffu, s, o);
    float scale = rsqrtf(s * (1.0f / 24.0f) + 1e-5f) * nw[c];
    if (lane < HW) g_xn[(n * DM + c) * NPOS + h * HW + lane] = v * scale;
}

// ---------------- 3x3 conv 96 -> 384 (in_proj), depth kernel = 1 ----------------
// grid: (24 rows h, 6 channel tiles of 64, 2 batch), 128 threads
// thread: 2 output channels x 6 w positions
__global__ void conv_kernel(const float* __restrict__ ipw) {
    __shared__ float S[96 * 3 * 26];   // [ci][kh][w padded -1..24]
    int h = blockIdx.x, ct = blockIdx.y, n = blockIdx.z;
    int tid = threadIdx.x;

    for (int idx = tid; idx < 96 * 78; idx += 128) {
        int ci = idx / 78, r = idx % 78;
        int kh = r / 26, wp = r % 26;
        int hh = h + kh - 1, w = wp - 1;
        float v = 0.f;
        if (hh >= 0 && hh < HW && w >= 0 && w < HW)
            v = g_xn[(n * DM + ci) * NPOS + hh * HW + w];
        S[idx] = v;
    }
    __syncthreads();

    int c  = ct * 64 + (tid >> 2) * 2;   // output channel pair base
    int w0 = (tid & 3) * 6;              // 6 outputs in w
    const float* wq0 = ipw + (size_t)c * 864;
    const float* wq1 = wq0 + 864;

    float a0[6] = {0, 0, 0, 0, 0, 0};
    float a1[6] = {0, 0, 0, 0, 0, 0};

    for (int ci = 0; ci < 96; ci++) {
        const float* srow = S + ci * 78 + w0;
        const float* q0 = wq0 + ci * 9;
        const float* q1 = wq1 + ci * 9;
        #pragma unroll
        for (int kh = 0; kh < 3; kh++) {
            float in[8];
            #pragma unroll
            for (int j = 0; j < 8; j++) in[j] = srow[kh * 26 + j];
            float b00 = q0[kh * 3 + 0], b01 = q0[kh * 3 + 1], b02 = q0[kh * 3 + 2];
            float b10 = q1[kh * 3 + 0], b11 = q1[kh * 3 + 1], b12 = q1[kh * 3 + 2];
            #pragma unroll
            for (int i = 0; i < 6; i++) {
                a0[i] += b00 * in[i] + b01 * in[i + 1] + b02 * in[i + 2];
                a1[i] += b10 * in[i] + b11 * in[i + 1] + b12 * in[i + 2];
            }
        }
    }
    float* o0 = g_xz + ((size_t)(n * 384 + c)) * NPOS + h * HW + w0;
    #pragma unroll
    for (int i = 0; i < 6; i++) { o0[i] = a0[i]; o0[NPOS + i] = a1[i]; }
}

// ---------------- fused pointwise chain per position ----------------
// grid: 1152 blocks (one per (n,h,w)), 192 threads
__global__ void fused_kernel(const float* __restrict__ cw,  const float* __restrict__ cb,
                             const float* __restrict__ xpw, const float* __restrict__ dtw,
                             const float* __restrict__ dtb, const float* __restrict__ Dp,
                             const float* __restrict__ opw,
                             const float* __restrict__ src, long cstride, long nstride,
                             float* __restrict__ dst) {
    __shared__ float xi_s[192];
    __shared__ float g_s[192];
    __shared__ float dbc_s[38];
    __shared__ float part[192];

    int p = blockIdx.x;
    int n = p / NPOS, rem = p % NPOS;
    int tid = threadIdx.x;

    const float* xzb = g_xz + (size_t)n * 384 * NPOS + rem;
    float v  = xzb[tid * NPOS];
    float zv = xzb[(192 + tid) * NPOS];

    // conv1d at depth 0: only tap 3 survives; then silu
    float pre = cw[tid * 4 + 3] * v + cb[tid];
    float xi = pre / (1.f + expf(-pre));
    xi_s[tid] = xi;
    __syncthreads();

    // dbc = x_proj @ xi : 38 dot-products of length 192, one warp per j-stripe
    int wid = tid >> 5, lane = tid & 31;
    for (int j = wid; j < 38; j += 6) {
        const float* xp = xpw + j * 192;
        float s = 0.f;
        #pragma unroll
        for (int k = 0; k < 6; k++) s += xp[lane + 32 * k] * xi_s[lane + 32 * k];
        #pragma unroll
        for (int o = 16; o; o >>= 1) s += __shfl_xor_sync(0xffffffffu, s, o);
        if (lane == 0) dbc_s[j] = s;
    }
    __syncthreads();

    // scalar B . C
    float bc = 0.f;
    #pragma unroll
    for (int s = 0; s < 16; s++) bc += dbc_s[6 + s] * dbc_s[22 + s];

    // delta = softplus(dt_proj @ dbc[:6] + bias)
    const float* dw = dtw + tid * 6;
    float d = dtb[tid];
    #pragma unroll
    for (int r = 0; r < 6; r++) d += dw[r] * dbc_s[r];
    float sp = fmaxf(d, 0.f) + log1pf(expf(-fabsf(d)));

    // y = xi * (delta*bc + D);  g = y * silu(z)
    float y = xi * (sp * bc + Dp[tid]);
    float g = y * (zv / (1.f + expf(-zv)));
    g_s[tid] = g;
    __syncthreads();

    // out_proj: 96 outputs, each 192-dot split across two half-threads
    int half = tid / 96, k = tid % 96;
    const float* ow = opw + k * 192 + half * 96;
    const float* gs = g_s + half * 96;
    float s = 0.f;
    #pragma unroll
    for (int c4 = 0; c4 < 96; c4 += 4) {
        float4 wv = *(const float4*)(ow + c4);
        s += wv.x * gs[c4] + wv.y * gs[c4 + 1] + wv.z * gs[c4 + 2] + wv.w * gs[c4 + 3];
    }
    part[tid] = s;
    __syncthreads();

    if (tid < 96) {
        float o = part[tid] + part[tid + 96]
                + src[(size_t)n * nstride + (size_t)tid * cstride + rem];
        dst[((size_t)n * 96 + tid) * NPOS + rem] = o;
    }
}

extern "C" void kernel_launch(void* const* d_in, const int* in_sizes, int n_in,
                              void* d_out, int out_size) {
    const float* x         = (const float*)d_in[0];
    const float* in_proj_w = (const float*)d_in[1];
    const float* conv1d_w  = (const float*)d_in[2];
    const float* conv1d_b  = (const float*)d_in[3];
    const float* x_proj_w  = (const float*)d_in[4];
    const float* dt_proj_w = (const float*)d_in[5];
    const float* dt_proj_b = (const float*)d_in[6];
    // d_in[7] = A_log : provably unused (hs[depth 0] = BX[depth 0])
    const float* Dp        = (const float*)d_in[8];
    const float* out_proj_w= (const float*)d_in[9];
    const float* norm_w    = (const float*)d_in[10];
    float* out = (float*)d_out;

    float* mid = nullptr;
    cudaGetSymbolAddress((void**)&mid, g_mid);

    // per-layer weight strides
    const int IPW = 384 * 96 * 9;   // 331776
    const int CW = 192 * 4, CB = 192, XPW = 38 * 192, DTW = 192 * 6, DTB = 192;
    const int DD = 192, OPW = 96 * 192, NW = 96;

    // ---- layer 0: input = original x depth-0 slice (strided view) ----
    {
        long cs = 8L * NPOS;            // channel stride in x
        long ns = 96L * 8L * NPOS;      // batch stride in x
        rms_kernel<<<576, 256>>>(x, cs, ns, norm_w + 0 * NW);
        conv_kernel<<<dim3(24, 6, 2), 128>>>(in_proj_w + 0 * IPW);
        fused_kernel<<<1152, 192>>>(conv1d_w + 0 * CW, conv1d_b + 0 * CB,
                                    x_proj_w + 0 * XPW, dt_proj_w + 0 * DTW,
                                    dt_proj_b + 0 * DTB, Dp + 0 * DD,
                                    out_proj_w + 0 * OPW,
                                    x, cs, ns, mid);
    }
    // ---- layer 1: input = g_mid (contiguous) ----
    {
        long cs = (long)NPOS;
        long ns = 96L * NPOS;
        rms_kernel<<<576, 256>>>(mid, cs, ns, norm_w + 1 * NW);
        conv_kernel<<<dim3(24, 6, 2), 128>>>(in_proj_w + 1 * IPW);
        fused_kernel<<<1152, 192>>>(conv1d_w + 1 * CW, conv1d_b + 1 * CB,
                                    x_proj_w + 1 * XPW, dt_proj_w + 1 * DTW,
                                    dt_proj_b + 1 * DTB, Dp + 1 * DD,
                                    out_proj_w + 1 * OPW,
                                    mid, cs, ns, out);
    }
}

// round 2
// speedup vs baseline: 1.6762x; 1.6762x over previous
#include <cuda_runtime.h>
#include <math.h>

#define HW 24
#define NPOS 576
#define WPAD 36

// Scratch (__device__ globals: allocation-free rule)
__device__ float g_xz[2 * 384 * NPOS];
__device__ float g_mid[2 * 96 * NPOS];
__device__ float g_wT[2 * 864 * 384];

// ---------- packed f32x2 helpers ----------
__device__ __forceinline__ void ffma2(unsigned long long& acc,
                                      unsigned long long a, unsigned long long b) {
    asm("fma.rn.f32x2 %0, %1, %2, %0;" : "+l"(acc) : "l"(a), "l"(b));
}
__device__ __forceinline__ unsigned long long dup2(float v) {
    float2 f; f.x = v; f.y = v;
    return *reinterpret_cast<unsigned long long*>(&f);
}

// ---------- weight transpose: [co][ci*9+t] -> [ci*9+t][co] ----------
__global__ void wt_kernel(const float* __restrict__ ipw) {
    __shared__ float tile[32][33];
    int r0 = blockIdx.x * 32, c0 = blockIdx.y * 32, l = blockIdx.z;
    int tx = threadIdx.x, ty = threadIdx.y;   // (32, 8)
    const float* src = ipw + (size_t)l * 331776;
    float* dst = g_wT + (size_t)l * 331776;
    #pragma unroll
    for (int i = 0; i < 4; i++)
        tile[ty + 8 * i][tx] = src[(size_t)(c0 + ty + 8 * i) * 864 + r0 + tx];
    __syncthreads();
    #pragma unroll
    for (int i = 0; i < 4; i++)
        dst[(size_t)(r0 + ty + 8 * i) * 384 + c0 + tx] = tile[tx][ty + 8 * i];
}

// ---------- fused rmsnorm + 3x3 conv (96 -> 384) ----------
// block: 32 out-ch x (4 h-rows x 24 w), 256 threads; grid (6 htile, 12 ctile, 2 n)
__global__ void __launch_bounds__(256, 1)
conv_kernel(const float* __restrict__ wT,
            const float* __restrict__ src, long cs, long ns,
            const float* __restrict__ nw,
            float* __restrict__ outp) {
    extern __shared__ float sm[];
    float* S  = sm;              // [96][6][26]  raw -> normalized input
    float* RS = sm + 14976;      // [576] row scales
    float* W  = sm + 15552;      // [864][WPAD]  weights (co chunk of 32)

    int h0 = blockIdx.x * 4;
    int ct = blockIdx.y;
    int n  = blockIdx.z;
    int tid = threadIdx.x;

    // stage raw input rows (with h halo, zero-padded)
    const float* sb = src + (size_t)n * ns;
    for (int idx = tid; idx < 96 * 6 * 24; idx += 256) {
        int w = idx % 24;
        int row = idx / 24;               // ci*6 + hr
        int hr = row % 6, ci = row / 6;
        int hh = h0 + hr - 1;
        float v = 0.f;
        if (hh >= 0 && hh < 24) v = sb[(size_t)ci * cs + hh * 24 + w];
        S[row * 26 + 1 + w] = v;
    }
    for (int row = tid; row < 576; row += 256) { S[row * 26] = 0.f; S[row * 26 + 25] = 0.f; }

    // stage weights: 864 rows x 32 co
    {
        const float* wsrc = wT + ct * 32;
        int fq = tid & 7;                 // float4 within row
        int r  = tid >> 3;                // 0..31
        for (; r < 864; r += 32) {
            float4 v = *(const float4*)(wsrc + (size_t)r * 384 + fq * 4);
            *(float4*)(W + r * WPAD + fq * 4) = v;
        }
    }
    __syncthreads();

    // rms row scales (per (ci, h-row), mean over 24 w)
    for (int row = tid; row < 576; row += 256) {
        const float* p = S + row * 26 + 1;
        float s = 0.f;
        #pragma unroll
        for (int j = 0; j < 24; j++) s += p[j] * p[j];
        RS[row] = rsqrtf(s * (1.f / 24.f) + 1e-5f) * nw[row / 6];
    }
    __syncthreads();
    for (int idx = tid; idx < 14976; idx += 256) S[idx] *= RS[idx / 26];
    __syncthreads();

    // compute: thread = 4 out-ch (2 f32x2 pairs) x 3 w positions
    int cq = tid >> 5;                    // 0..7 -> co_local = cq*4
    int pq = tid & 31;
    int hl = pq >> 3;                     // 0..3
    int w0 = (pq & 7) * 3;                // 0,3,...,21

    unsigned long long acc[2][3];
    #pragma unroll
    for (int a = 0; a < 2; a++)
        #pragma unroll
        for (int w = 0; w < 3; w++) acc[a][w] = 0ull;

    const float* Wc = W + cq * 4;
    const float* Sc = S + hl * 26 + w0;
    for (int ci = 0; ci < 96; ci++) {
        const float* Sr = Sc + ci * 156;
        const float* Wr = Wc + ci * 9 * WPAD;
        #pragma unroll
        for (int kh = 0; kh < 3; kh++) {
            const float* rp = Sr + kh * 26;
            unsigned long long ind[5];
            #pragma unroll
            for (int j = 0; j < 5; j++) ind[j] = dup2(rp[j]);
            #pragma unroll
            for (int kw = 0; kw < 3; kw++) {
                const float* wp = Wr + (kh * 3 + kw) * WPAD;
                unsigned long long w01 = *(const unsigned long long*)(wp);
                unsigned long long w23 = *(const unsigned long long*)(wp + 2);
                #pragma unroll
                for (int w = 0; w < 3; w++) {
                    ffma2(acc[0][w], w01, ind[w + kw]);
                    ffma2(acc[1][w], w23, ind[w + kw]);
                }
            }
        }
    }

    float* ob = outp + ((size_t)(n * 384 + ct * 32 + cq * 4)) * NPOS + (h0 + hl) * 24 + w0;
    #pragma unroll
    for (int a = 0; a < 2; a++) {
        float* o0 = ob + (size_t)(2 * a) * NPOS;
        #pragma unroll
        for (int w = 0; w < 3; w++) {
            float2 v = *(float2*)&acc[a][w];
            o0[w] = v.x;
            o0[NPOS + w] = v.y;
        }
    }
}

// ---------- fused pointwise chain + GEMVs over 16-position tiles ----------
// 192 threads, grid (36 ptiles, 2 n)
__global__ void __launch_bounds__(192, 1)
fused_kernel(const float* __restrict__ cw,  const float* __restrict__ cb,
             const float* __restrict__ xpw, const float* __restrict__ dtw,
             const float* __restrict__ dtb, const float* __restrict__ Dp,
             const float* __restrict__ opw,
             const float* __restrict__ resid, long cs, long ns,
             float* __restrict__ dst) {
    extern __shared__ float sm[];
    float* xi_s  = sm;                    // [192][16]
    float* dbc_s = sm + 3072;             // [38][16]
    float* bc_s  = sm + 3680;             // [16]
    float* xpw_s = sm + 3696;             // [38][193]
    float* opw_s = sm + 3696 + 7334;      // [96][193]

    int tid = threadIdx.x;
    int p0 = blockIdx.x * 16;
    int n  = blockIdx.y;

    for (int idx = tid; idx < 38 * 192; idx += 192)
        xpw_s[(idx / 192) * 193 + (idx % 192)] = xpw[idx];
    for (int idx = tid; idx < 96 * 192; idx += 192)
        opw_s[(idx / 192) * 193 + (idx % 192)] = opw[idx];

    // xi = silu(conv1d depth-0 tap + bias)
    const float* xzb = g_xz + (size_t)n * 384 * NPOS + p0;
    for (int idx = tid; idx < 3072; idx += 192) {
        int c = idx >> 4, p = idx & 15;
        float v = xzb[(size_t)c * NPOS + p];
        float pre = __ldg(cw + c * 4 + 3) * v + __ldg(cb + c);
        xi_s[idx] = pre / (1.f + __expf(-pre));
    }
    __syncthreads();

    // dbc[38][16] = x_proj @ xi
    {
        int pp = tid & 7;
        int jg = tid >> 3;                // 0..23
        for (int j = jg; j < 38; j += 24) {
            unsigned long long a = 0ull;
            const float* wr = xpw_s + j * 193;
            const float* xr = xi_s + pp * 2;
            #pragma unroll 4
            for (int c = 0; c < 192; c++)
                ffma2(a, dup2(wr[c]), *(const unsigned long long*)(xr + c * 16));
            *(unsigned long long*)(dbc_s + j * 16 + pp * 2) = a;
        }
    }
    __syncthreads();

    // bc[p] = B . C  (scalar per position)
    if (tid < 16) {
        float s = 0.f;
        #pragma unroll
        for (int q = 0; q < 16; q++)
            s += dbc_s[(6 + q) * 16 + tid] * dbc_s[(22 + q) * 16 + tid];
        bc_s[tid] = s;
    }
    __syncthreads();

    // delta -> y -> gate; overwrite xi_s with g
    {
        int c = tid;
        float dw[6];
        #pragma unroll
        for (int r = 0; r < 6; r++) dw[r] = __ldg(dtw + c * 6 + r);
        float bconst = __ldg(dtb + c);
        float Dc = __ldg(Dp + c);
        const float* zrow = xzb + (size_t)(192 + c) * NPOS;
        float zr[16];
        #pragma unroll
        for (int q = 0; q < 4; q++)
            *(float4*)(zr + q * 4) = *(const float4*)(zrow + q * 4);
        #pragma unroll
        for (int p = 0; p < 16; p++) {
            float d = bconst;
            #pragma unroll
            for (int r = 0; r < 6; r++) d += dw[r] * dbc_s[r * 16 + p];
            float sp = fmaxf(d, 0.f) + log1pf(__expf(-fabsf(d)));
            float z = zr[p];
            float g = xi_s[c * 16 + p] * (sp * bc_s[p] + Dc) * (z / (1.f + __expf(-z)));
            xi_s[c * 16 + p] = g;
        }
    }
    __syncthreads();

    // out = out_proj @ g + residual
    {
        int pp = tid & 7;
        int kg = tid >> 3;                // 0..23 -> 4 k each
        unsigned long long a[4] = {0ull, 0ull, 0ull, 0ull};
        const float* xr = xi_s + pp * 2;
        for (int c = 0; c < 192; c++) {
            unsigned long long gv = *(const unsigned long long*)(xr + c * 16);
            #pragma unroll
            for (int i = 0; i < 4; i++)
                ffma2(a[i], dup2(opw_s[(kg * 4 + i) * 193 + c]), gv);
        }
        #pragma unroll
        for (int i = 0; i < 4; i++) {
            int k = kg * 4 + i;
            float2 v = *(float2*)&a[i];
            const float* rb = resid + (size_t)n * ns + (size_t)k * cs + p0 + pp * 2;
            v.x += rb[0];
            v.y += rb[1];
            *(float2*)(dst + (size_t)(n * 96 + k) * NPOS + p0 + pp * 2) = v;
        }
    }
}

extern "C" void kernel_launch(void* const* d_in, const int* in_sizes, int n_in,
                              void* d_out, int out_size) {
    const float* x          = (const float*)d_in[0];
    const float* in_proj_w  = (const float*)d_in[1];
    const float* conv1d_w   = (const float*)d_in[2];
    const float* conv1d_b   = (const float*)d_in[3];
    const float* x_proj_w   = (const float*)d_in[4];
    const float* dt_proj_w  = (const float*)d_in[5];
    const float* dt_proj_b  = (const float*)d_in[6];
    // d_in[7] = A_log : unused (hs at depth 0 == BX at depth 0)
    const float* Dp         = (const float*)d_in[8];
    const float* out_proj_w = (const float*)d_in[9];
    const float* norm_w     = (const float*)d_in[10];
    float* out = (float*)d_out;

    float *xz = nullptr, *mid = nullptr, *wT = nullptr;
    cudaGetSymbolAddress((void**)&xz, g_xz);
    cudaGetSymbolAddress((void**)&mid, g_mid);
    cudaGetSymbolAddress((void**)&wT, g_wT);

    const int CONV_SMEM  = (14976 + 576 + 864 * WPAD) * 4;   // 186624
    const int FUSED_SMEM = (3696 + 7334 + 96 * 193) * 4;     // 118232
    cudaFuncSetAttribute(conv_kernel,  cudaFuncAttributeMaxDynamicSharedMemorySize, CONV_SMEM);
    cudaFuncSetAttribute(fused_kernel, cudaFuncAttributeMaxDynamicSharedMemorySize, FUSED_SMEM);

    wt_kernel<<<dim3(27, 12, 2), dim3(32, 8)>>>(in_proj_w);

    // layer 0: input = x depth-0 slice (strided view)
    {
        long cs = 8L * NPOS, ns = 96L * 8L * NPOS;
        conv_kernel<<<dim3(6, 12, 2), 256, CONV_SMEM>>>(wT, x, cs, ns, norm_w, xz);
        fused_kernel<<<dim3(36, 2), 192, FUSED_SMEM>>>(
            conv1d_w, conv1d_b, x_proj_w, dt_proj_w, dt_proj_b, Dp, out_proj_w,
            x, cs, ns, mid);
    }
    // layer 1: input = mid (contiguous)
    {
        long cs = (long)NPOS, ns = 96L * NPOS;
        conv_kernel<<<dim3(6, 12, 2), 256, CONV_SMEM>>>(
            wT + 331776, mid, cs, ns, norm_w + 96, xz);
        fused_kernel<<<dim3(36, 2), 192, FUSED_SMEM>>>(
            conv1d_w + 768, conv1d_b + 192, x_proj_w + 7296, dt_proj_w + 1152,
            dt_proj_b + 192, Dp + 192, out_proj_w + 18432,
            mid, cs, ns, out);
    }
}

// round 3
// speedup vs baseline: 2.1779x; 1.2993x over previous
#include <cuda_runtime.h>
#include <math.h>

#define HW 24
#define NPOS 576
#define XZH 442368            // one K-half of xz: 2n * 384 * 576

// Scratch (__device__ globals: allocation-free rule)
__device__ float g_xz[2 * XZH];          // [khalf][n][384][576]
__device__ float g_mid[2 * 96 * NPOS];
__device__ float g_wT[2 * 864 * 384];

typedef unsigned long long ull;

__device__ __forceinline__ void ffma2(ull& acc, ull a, ull b) {
    asm("fma.rn.f32x2 %0, %1, %2, %0;" : "+l"(acc) : "l"(a), "l"(b));
}
__device__ __forceinline__ ull dup2(float v) {
    ull r;
    asm("mov.b64 %0, {%1, %1};" : "=l"(r) : "f"(v));
    return r;
}

// ---------- weight transpose: [co][ci*9+t] -> [ci*9+t][co] ----------
__global__ void wt_kernel(const float* __restrict__ ipw) {
    __shared__ float tile[32][33];
    int r0 = blockIdx.x * 32, c0 = blockIdx.y * 32, l = blockIdx.z;
    int tx = threadIdx.x, ty = threadIdx.y;   // (32, 8)
    const float* src = ipw + (size_t)l * 331776;
    float* dst = g_wT + (size_t)l * 331776;
    #pragma unroll
    for (int i = 0; i < 4; i++)
        tile[ty + 8 * i][tx] = src[(size_t)(c0 + ty + 8 * i) * 864 + r0 + tx];
    __syncthreads();
    #pragma unroll
    for (int i = 0; i < 4; i++)
        dst[(size_t)(r0 + ty + 8 * i) * 384 + c0 + tx] = tile[tx][ty + 8 * i];
}

// ---------- fused rmsnorm + 3x3 conv (96 -> 384), K-split by 2 ----------
// block: 64 co x (4h x 24w), 48-ci half; 256 threads
// grid: (6 htile, 6 ctile, 4 = n*2 + khalf)
// thread tile: 4 co x 2 h x 3 w, packed f32x2 over co-pairs
__global__ void __launch_bounds__(256, 1)
conv_kernel(const float* __restrict__ wT,
            const float* __restrict__ src, long cs, long ns,
            const float* __restrict__ nw,
            float* __restrict__ outp) {
    extern __shared__ float sm[];
    float* S  = sm;            // [48][6][26] = 7488
    float* RS = sm + 7488;     // [288]
    float* W  = sm + 7776;     // [432][68] = 29376

    int h0  = blockIdx.x * 4;
    int ct  = blockIdx.y;
    int n   = blockIdx.z >> 1;
    int ks  = blockIdx.z & 1;
    int ci0 = ks * 48;
    int tid = threadIdx.x;

    // stage raw input rows (48 ci, 6 h rows with halo, zero-padded w)
    const float* sb = src + (size_t)n * ns + (size_t)ci0 * cs;
    for (int idx = tid; idx < 48 * 6 * 24; idx += 256) {
        int w = idx % 24;
        int row = idx / 24;            // ci*6 + hr
        int hr = row % 6, ci = row / 6;
        int hh = h0 + hr - 1;
        float v = 0.f;
        if (hh >= 0 && hh < 24) v = sb[(size_t)ci * cs + hh * 24 + w];
        S[row * 26 + 1 + w] = v;
    }
    for (int row = tid; row < 288; row += 256) { S[row * 26] = 0.f; S[row * 26 + 25] = 0.f; }

    // stage weights: rows [ci0*9, ci0*9+432), cols [ct*64, +64)
    {
        const float* wsrc = wT + (size_t)(ci0 * 9) * 384 + ct * 64;
        for (int idx = tid; idx < 432 * 16; idx += 256) {
            int r = idx >> 4, fq = idx & 15;
            *(float4*)(W + r * 68 + fq * 4) = *(const float4*)(wsrc + (size_t)r * 384 + fq * 4);
        }
    }
    __syncthreads();

    // rms row scales (per (ci, h-row), mean over 24 w)
    for (int row = tid; row < 288; row += 256) {
        const float* p = S + row * 26 + 1;
        float s = 0.f;
        #pragma unroll
        for (int j = 0; j < 24; j++) s += p[j] * p[j];
        RS[row] = rsqrtf(s * (1.f / 24.f) + 1e-5f) * nw[ci0 + row / 6];
    }
    __syncthreads();
    for (int idx = tid; idx < 7488; idx += 256) S[idx] *= RS[idx / 26];
    __syncthreads();

    // compute
    int g  = tid >> 4;                 // 0..15 cogroup -> co_local = g*4
    int q  = tid & 15;
    int hl = (q >> 3) * 2;             // 0 or 2
    int w0 = (q & 7) * 3;              // 0..21 (also padded col base)

    ull acc[2][2][3];
    #pragma unroll
    for (int a = 0; a < 2; a++)
        #pragma unroll
        for (int dh = 0; dh < 2; dh++)
            #pragma unroll
            for (int dw = 0; dw < 3; dw++) acc[a][dh][dw] = 0ull;

    const float* Sbase = S + hl * 26 + w0;
    const float* Wbase = W + g * 4;

    #pragma unroll 1
    for (int ci = 0; ci < 48; ci++) {
        const float* Sr = Sbase + ci * 156;
        ull ind[4][5];
        #pragma unroll
        for (int r = 0; r < 4; r++)
            #pragma unroll
            for (int j = 0; j < 5; j++)
                ind[r][j] = dup2(Sr[r * 26 + j]);

        const float* Wr = Wbase + ci * 9 * 68;
        #pragma unroll
        for (int kh = 0; kh < 3; kh++) {
            #pragma unroll
            for (int kw = 0; kw < 3; kw++) {
                const float4 wv = *(const float4*)(Wr + (kh * 3 + kw) * 68);
                ull w01 = *(const ull*)&wv.x;
                ull w23 = *(const ull*)&wv.z;
                #pragma unroll
                for (int dh = 0; dh < 2; dh++) {
                    #pragma unroll
                    for (int dw = 0; dw < 3; dw++) {
                        ffma2(acc[0][dh][dw], w01, ind[dh + kh][dw + kw]);
                        ffma2(acc[1][dh][dw], w23, ind[dh + kh][dw + kw]);
                    }
                }
            }
        }
    }

    int cobase = ct * 64 + g * 4;
    float* ob = outp + (size_t)ks * XZH
              + ((size_t)(n * 384 + cobase)) * NPOS + (h0 + hl) * 24 + w0;
    #pragma unroll
    for (int a = 0; a < 2; a++) {
        #pragma unroll
        for (int dh = 0; dh < 2; dh++) {
            #pragma unroll
            for (int dw = 0; dw < 3; dw++) {
                float2 v = *(float2*)&acc[a][dh][dw];
                ob[(size_t)(2 * a) * NPOS + dh * 24 + dw] = v.x;
                ob[(size_t)(2 * a + 1) * NPOS + dh * 24 + dw] = v.y;
            }
        }
    }
}

// ---------- fused pointwise chain + GEMVs over 16-position tiles ----------
// 192 threads, grid (36 ptiles, 2 n)
__global__ void __launch_bounds__(192, 1)
fused_kernel(const float* __restrict__ cw,  const float* __restrict__ cb,
             const float* __restrict__ xpw, const float* __restrict__ dtw,
             const float* __restrict__ dtb, const float* __restrict__ Dp,
             const float* __restrict__ opw,
             const float* __restrict__ resid, long cs, long ns,
             float* __restrict__ dst) {
    extern __shared__ float sm[];
    float* xi_s  = sm;                    // [192][16]
    float* dbc_s = sm + 3072;             // [38][16]
    float* bc_s  = sm + 3680;             // [16]
    float* xpw_s = sm + 3696;             // [38][193]
    float* opw_s = sm + 3696 + 7334;      // [96][193]

    int tid = threadIdx.x;
    int p0 = blockIdx.x * 16;
    int n  = blockIdx.y;

    for (int idx = tid; idx < 38 * 192; idx += 192)
        xpw_s[(idx / 192) * 193 + (idx % 192)] = xpw[idx];
    for (int idx = tid; idx < 96 * 192; idx += 192)
        opw_s[(idx / 192) * 193 + (idx % 192)] = opw[idx];

    // xi = silu(conv1d depth-0 tap + bias); sum the two K-halves
    const float* xzb = g_xz + (size_t)n * 384 * NPOS + p0;
    for (int idx = tid; idx < 3072; idx += 192) {
        int c = idx >> 4, p = idx & 15;
        size_t o = (size_t)c * NPOS + p;
        float v = xzb[o] + xzb[XZH + o];
        float pre = __ldg(cw + c * 4 + 3) * v + __ldg(cb + c);
        xi_s[idx] = pre / (1.f + __expf(-pre));
    }
    __syncthreads();

    // dbc[38][16] = x_proj @ xi
    {
        int pp = tid & 7;
        int jg = tid >> 3;                // 0..23
        for (int j = jg; j < 38; j += 24) {
            ull a = 0ull;
            const float* wr = xpw_s + j * 193;
            const float* xr = xi_s + pp * 2;
            #pragma unroll 4
            for (int c = 0; c < 192; c++)
                ffma2(a, dup2(wr[c]), *(const ull*)(xr + c * 16));
            *(ull*)(dbc_s + j * 16 + pp * 2) = a;
        }
    }
    __syncthreads();

    // bc[p] = B . C  (scalar per position)
    if (tid < 16) {
        float s = 0.f;
        #pragma unroll
        for (int qq = 0; qq < 16; qq++)
            s += dbc_s[(6 + qq) * 16 + tid] * dbc_s[(22 + qq) * 16 + tid];
        bc_s[tid] = s;
    }
    __syncthreads();

    // delta -> y -> gate; overwrite xi_s with g
    {
        int c = tid;
        float dw[6];
        #pragma unroll
        for (int r = 0; r < 6; r++) dw[r] = __ldg(dtw + c * 6 + r);
        float bconst = __ldg(dtb + c);
        float Dc = __ldg(Dp + c);
        const float* zrow = xzb + (size_t)(192 + c) * NPOS;
        #pragma unroll
        for (int p = 0; p < 16; p++) {
            float d = bconst;
            #pragma unroll
            for (int r = 0; r < 6; r++) d += dw[r] * dbc_s[r * 16 + p];
            float sp = fmaxf(d, 0.f) + log1pf(__expf(-fabsf(d)));
            float z = zrow[p] + zrow[XZH + p];
            float g = xi_s[c * 16 + p] * (sp * bc_s[p] + Dc) * (z / (1.f + __expf(-z)));
            xi_s[c * 16 + p] = g;
        }
    }
    __syncthreads();

    // out = out_proj @ g + residual
    {
        int pp = tid & 7;
        int kg = tid >> 3;                // 0..23 -> 4 k each
        ull a[4] = {0ull, 0ull, 0ull, 0ull};
        const float* xr = xi_s + pp * 2;
        for (int c = 0; c < 192; c++) {
            ull gv = *(const ull*)(xr + c * 16);
            #pragma unroll
            for (int i = 0; i < 4; i++)
                ffma2(a[i], dup2(opw_s[(kg * 4 + i) * 193 + c]), gv);
        }
        #pragma unroll
        for (int i = 0; i < 4; i++) {
            int k = kg * 4 + i;
            float2 v = *(float2*)&a[i];
            const float* rb = resid + (size_t)n * ns + (size_t)k * cs + p0 + pp * 2;
            v.x += rb[0];
            v.y += rb[1];
            *(float2*)(dst + (size_t)(n * 96 + k) * NPOS + p0 + pp * 2) = v;
        }
    }
}

extern "C" void kernel_launch(void* const* d_in, const int* in_sizes, int n_in,
                              void* d_out, int out_size) {
    const float* x          = (const float*)d_in[0];
    const float* in_proj_w  = (const float*)d_in[1];
    const float* conv1d_w   = (const float*)d_in[2];
    const float* conv1d_b   = (const float*)d_in[3];
    const float* x_proj_w   = (const float*)d_in[4];
    const float* dt_proj_w  = (const float*)d_in[5];
    const float* dt_proj_b  = (const float*)d_in[6];
    // d_in[7] = A_log : unused (hs at depth 0 == BX at depth 0)
    const float* Dp         = (const float*)d_in[8];
    const float* out_proj_w = (const float*)d_in[9];
    const float* norm_w     = (const float*)d_in[10];
    float* out = (float*)d_out;

    float *xz = nullptr, *mid = nullptr, *wT = nullptr;
    cudaGetSymbolAddress((void**)&xz, g_xz);
    cudaGetSymbolAddress((void**)&mid, g_mid);
    cudaGetSymbolAddress((void**)&wT, g_wT);

    const int CONV_SMEM  = (7488 + 288 + 432 * 68) * 4;      // 148608
    const int FUSED_SMEM = (3696 + 7334 + 96 * 193) * 4;     // 118232
    cudaFuncSetAttribute(conv_kernel,  cudaFuncAttributeMaxDynamicSharedMemorySize, CONV_SMEM);
    cudaFuncSetAttribute(fused_kernel, cudaFuncAttributeMaxDynamicSharedMemorySize, FUSED_SMEM);

    wt_kernel<<<dim3(27, 12, 2), dim3(32, 8)>>>(in_proj_w);

    // layer 0: input = x depth-0 slice (strided view)
    {
        long cs = 8L * NPOS, ns = 96L * 8L * NPOS;
        conv_kernel<<<dim3(6, 6, 4), 256, CONV_SMEM>>>(wT, x, cs, ns, norm_w, xz);
        fused_kernel<<<dim3(36, 2), 192, FUSED_SMEM>>>(
            conv1d_w, conv1d_b, x_proj_w, dt_proj_w, dt_proj_b, Dp, out_proj_w,
            x, cs, ns, mid);
    }
    // layer 1: input = mid (contiguous)
    {
        long cs = (long)NPOS, ns = 96L * NPOS;
        conv_kernel<<<dim3(6, 6, 4), 256, CONV_SMEM>>>(
            wT + 331776, mid, cs, ns, norm_w + 96, xz);
        fused_kernel<<<dim3(36, 2), 192, FUSED_SMEM>>>(
            conv1d_w + 768, conv1d_b + 192, x_proj_w + 7296, dt_proj_w + 1152,
            dt_proj_b + 192, Dp + 192, out_proj_w + 18432,
            mid, cs, ns, out);
    }
}

// round 4
// speedup vs baseline: 2.3176x; 1.0641x over previous
#include <cuda_runtime.h>
#include <math.h>

#define HW 24
#define NPOS 576
#define XZQ 442368            // one K-quarter of xz: 2n * 384 * 576

// Scratch (__device__ globals: allocation-free rule)
__device__ float g_xz[4 * XZQ];          // [kq][n][384][576]
__device__ float g_mid[2 * 96 * NPOS];
__device__ float g_wT[2 * 864 * 384];

typedef unsigned long long ull;

__device__ __forceinline__ void ffma2(ull& acc, ull a, ull b) {
    asm("fma.rn.f32x2 %0, %1, %2, %0;" : "+l"(acc) : "l"(a), "l"(b));
}
__device__ __forceinline__ ull dup2(float v) {
    ull r;
    asm("mov.b64 %0, {%1, %1};" : "=l"(r) : "f"(v));
    return r;
}
__device__ __forceinline__ float2 up(ull a) { return *(float2*)&a; }

// ---------- weight transpose: [co][ci*9+t] -> [ci*9+t][co] ----------
__global__ void wt_kernel(const float* __restrict__ ipw) {
    __shared__ float tile[32][33];
    int r0 = blockIdx.x * 32, c0 = blockIdx.y * 32, l = blockIdx.z;
    int tx = threadIdx.x, ty = threadIdx.y;   // (32, 8)
    const float* src = ipw + (size_t)l * 331776;
    float* dst = g_wT + (size_t)l * 331776;
    #pragma unroll
    for (int i = 0; i < 4; i++)
        tile[ty + 8 * i][tx] = src[(size_t)(c0 + ty + 8 * i) * 864 + r0 + tx];
    __syncthreads();
    #pragma unroll
    for (int i = 0; i < 4; i++)
        dst[(size_t)(r0 + ty + 8 * i) * 384 + c0 + tx] = tile[tx][ty + 8 * i];
}

// ---------- fused rmsnorm + 3x3 conv (96 -> 384), K-split by 4 ----------
// block: 64 co x (4h x 24w), 24-ci quarter; 256 threads, 2 CTAs/SM
// grid: (6 htile, 6 ctile, 8 = n*4 + kq)
// thread tile: 4 co (2 f32x2 co-pairs) x 2 h x 3 w
__global__ void __launch_bounds__(256, 2)
conv_kernel(const float* __restrict__ wT,
            const float* __restrict__ src, long cs, long ns,
            const float* __restrict__ nw,
            float* __restrict__ outp) {
    extern __shared__ float sm[];
    float2* S2 = (float2*)sm;          // [144][28] float2, values duplicated
    float*  RS = sm + 144 * 56;        // [144]
    float*  W  = RS + 144;             // [216][68]

    int h0  = blockIdx.x * 4;
    int ct  = blockIdx.y;
    int n   = blockIdx.z >> 2;
    int kq  = blockIdx.z & 3;
    int ci0 = kq * 24;
    int tid = threadIdx.x;

    // stage raw input (24 ci, 6 h rows with halo), duplicated float2
    const float* sb = src + (size_t)n * ns + (size_t)ci0 * cs;
    for (int idx = tid; idx < 24 * 6 * 24; idx += 256) {
        int w = idx % 24;
        int row = idx / 24;            // ci*6 + hr
        int hr = row % 6, ci = row / 6;
        int hh = h0 + hr - 1;
        float v = 0.f;
        if (hh >= 0 && hh < 24) v = sb[(size_t)ci * cs + hh * 24 + w];
        S2[row * 28 + 1 + w] = make_float2(v, v);
    }
    if (tid < 144) {
        float2 z = make_float2(0.f, 0.f);
        S2[tid * 28] = z; S2[tid * 28 + 25] = z;
        S2[tid * 28 + 26] = z; S2[tid * 28 + 27] = z;
    }
    // stage weights: rows [ci0*9, +216), cols [ct*64, +64)
    {
        const float* wsrc = wT + (size_t)(ci0 * 9) * 384 + ct * 64;
        for (int idx = tid; idx < 216 * 16; idx += 256) {
            int r = idx >> 4, fq = idx & 15;
            *(float4*)(W + r * 68 + fq * 4) = *(const float4*)(wsrc + (size_t)r * 384 + fq * 4);
        }
    }
    __syncthreads();

    // rms row scales
    if (tid < 144) {
        const float2* p = S2 + tid * 28 + 1;
        float s = 0.f;
        #pragma unroll
        for (int j = 0; j < 24; j++) { float v = p[j].x; s += v * v; }
        RS[tid] = rsqrtf(s * (1.f / 24.f) + 1e-5f) * nw[ci0 + tid / 6];
    }
    __syncthreads();
    for (int idx = tid; idx < 144 * 56; idx += 256) sm[idx] *= RS[idx / 56];
    __syncthreads();

    // compute
    int g  = tid >> 4;                 // 0..15 -> co_local = g*4
    int q  = tid & 15;
    int hl = (q >> 3) * 2;             // 0 or 2
    int w0 = (q & 7) * 3;              // 0..21

    ull acc[2][2][3];
    #pragma unroll
    for (int a = 0; a < 2; a++)
        #pragma unroll
        for (int dh = 0; dh < 2; dh++)
            #pragma unroll
            for (int dw = 0; dw < 3; dw++) acc[a][dh][dw] = 0ull;

    const float2* Sbase = S2 + hl * 28 + w0;
    const float*  Wbase = W + g * 4;

    #pragma unroll 1
    for (int ci = 0; ci < 24; ci++) {
        const float2* Sr = Sbase + ci * 168;
        ull ind[4][5];
        #pragma unroll
        for (int r = 0; r < 4; r++)
            #pragma unroll
            for (int j = 0; j < 5; j++)
                ind[r][j] = *(const ull*)(Sr + r * 28 + j);

        const float* Wr = Wbase + ci * 9 * 68;
        #pragma unroll
        for (int kh = 0; kh < 3; kh++) {
            #pragma unroll
            for (int kw = 0; kw < 3; kw++) {
                const float4 wv = *(const float4*)(Wr + (kh * 3 + kw) * 68);
                ull w01 = *(const ull*)&wv.x;
                ull w23 = *(const ull*)&wv.z;
                #pragma unroll
                for (int dh = 0; dh < 2; dh++) {
                    #pragma unroll
                    for (int dw = 0; dw < 3; dw++) {
                        ffma2(acc[0][dh][dw], w01, ind[dh + kh][dw + kw]);
                        ffma2(acc[1][dh][dw], w23, ind[dh + kh][dw + kw]);
                    }
                }
            }
        }
    }

    int cobase = ct * 64 + g * 4;
    float* ob = outp + (size_t)kq * XZQ
              + ((size_t)(n * 384 + cobase)) * NPOS + (h0 + hl) * 24 + w0;
    #pragma unroll
    for (int a = 0; a < 2; a++) {
        #pragma unroll
        for (int dh = 0; dh < 2; dh++) {
            #pragma unroll
            for (int dw = 0; dw < 3; dw++) {
                float2 v = up(acc[a][dh][dw]);
                ob[(size_t)(2 * a) * NPOS + dh * 24 + dw] = v.x;
                ob[(size_t)(2 * a + 1) * NPOS + dh * 24 + dw] = v.y;
            }
        }
    }
}

// ---------- fused pointwise chain + GEMVs over 8-position tiles ----------
// 192 threads, grid (72 ptiles, 2 n)
__global__ void __launch_bounds__(192, 1)
fused_kernel(const float* __restrict__ cw,  const float* __restrict__ cb,
             const float* __restrict__ xpw, const float* __restrict__ dtw,
             const float* __restrict__ dtb, const float* __restrict__ Dp,
             const float* __restrict__ opw,
             const float* __restrict__ resid, long cs, long ns,
             float* __restrict__ dst) {
    extern __shared__ float sm[];
    float* xi_s  = sm;                    // [192][8]
    float* dbc_s = sm + 1536;             // [38][8]
    float* bc_s  = sm + 1840;             // [8]
    float* xpw_s = sm + 1848;             // [38][196]
    float* opw_s = sm + 1848 + 7448;      // [96][196]

    int tid = threadIdx.x;
    int p0 = blockIdx.x * 8;
    int n  = blockIdx.y;

    // stage weights (float4, padded stride 196 = conflict-free)
    for (int t = tid; t < 38 * 48; t += 192) {
        int r = t / 48, q = t % 48;
        *(float4*)(xpw_s + r * 196 + q * 4) = *(const float4*)(xpw + (size_t)r * 192 + q * 4);
    }
    for (int t = tid; t < 96 * 48; t += 192) {
        int r = t / 48, q = t % 48;
        *(float4*)(opw_s + r * 196 + q * 4) = *(const float4*)(opw + (size_t)r * 192 + q * 4);
    }

    // xi = silu(conv1d depth-0 tap + bias); sum the four K-quarters
    const float* xzb = g_xz + (size_t)n * 384 * NPOS + p0;
    for (int idx = tid; idx < 1536; idx += 192) {
        int c = idx >> 3, p = idx & 7;
        size_t o = (size_t)c * NPOS + p;
        float v = xzb[o] + xzb[XZQ + o] + xzb[2 * XZQ + o] + xzb[3 * XZQ + o];
        float pre = __ldg(cw + c * 4 + 3) * v + __ldg(cb + c);
        xi_s[idx] = pre / (1.f + __expf(-pre));
    }
    __syncthreads();

    // dbc[38][8] = x_proj @ xi  (two independent chains per thread)
    {
        int pp = tid & 3;
        int jg = tid >> 2;                // 0..47
        if (jg < 38) {
            ull a0 = 0ull, a1 = 0ull;
            const float* wr = xpw_s + jg * 196;
            const float* xr = xi_s + pp * 2;
            #pragma unroll 4
            for (int c = 0; c < 96; c++) {
                ffma2(a0, dup2(wr[c]),      *(const ull*)(xr + c * 8));
                ffma2(a1, dup2(wr[96 + c]), *(const ull*)(xr + (96 + c) * 8));
            }
            float2 v0 = up(a0), v1 = up(a1);
            float2 r = make_float2(v0.x + v1.x, v0.y + v1.y);
            *(float2*)(dbc_s + jg * 8 + pp * 2) = r;
        }
    }
    __syncthreads();

    // bc[p] = B . C
    if (tid < 8) {
        float s = 0.f;
        #pragma unroll
        for (int qq = 0; qq < 16; qq++)
            s += dbc_s[(6 + qq) * 8 + tid] * dbc_s[(22 + qq) * 8 + tid];
        bc_s[tid] = s;
    }
    __syncthreads();

    // delta -> y -> gate; overwrite xi_s with g
    {
        int c = tid;
        float dw[6];
        #pragma unroll
        for (int r = 0; r < 6; r++) dw[r] = __ldg(dtw + c * 6 + r);
        float bconst = __ldg(dtb + c);
        float Dc = __ldg(Dp + c);
        const float* zrow = xzb + (size_t)(192 + c) * NPOS;
        #pragma unroll
        for (int p = 0; p < 8; p++) {
            float d = bconst;
            #pragma unroll
            for (int r = 0; r < 6; r++) d += dw[r] * dbc_s[r * 8 + p];
            float sp = fmaxf(d, 0.f) + log1pf(__expf(-fabsf(d)));
            float z = zrow[p] + zrow[XZQ + p] + zrow[2 * XZQ + p] + zrow[3 * XZQ + p];
            float g = xi_s[c * 8 + p] * (sp * bc_s[p] + Dc) * (z / (1.f + __expf(-z)));
            xi_s[c * 8 + p] = g;
        }
    }
    __syncthreads();

    // out = out_proj @ g + residual  (4 independent chains per thread)
    {
        int pp = tid & 3;
        int kg = tid >> 2;                // 0..47 -> 2 k each
        ull a[2][2] = {{0ull, 0ull}, {0ull, 0ull}};
        const float* xr = xi_s + pp * 2;
        #pragma unroll 4
        for (int c = 0; c < 96; c++) {
            ull g0 = *(const ull*)(xr + c * 8);
            ull g1 = *(const ull*)(xr + (96 + c) * 8);
            #pragma unroll
            for (int i = 0; i < 2; i++) {
                ffma2(a[i][0], dup2(opw_s[(kg * 2 + i) * 196 + c]),      g0);
                ffma2(a[i][1], dup2(opw_s[(kg * 2 + i) * 196 + 96 + c]), g1);
            }
        }
        #pragma unroll
        for (int i = 0; i < 2; i++) {
            int k = kg * 2 + i;
            float2 v0 = up(a[i][0]), v1 = up(a[i][1]);
            float2 v = make_float2(v0.x + v1.x, v0.y + v1.y);
            const float* rb = resid + (size_t)n * ns + (size_t)k * cs + p0 + pp * 2;
            v.x += rb[0];
            v.y += rb[1];
            *(float2*)(dst + (size_t)(n * 96 + k) * NPOS + p0 + pp * 2) = v;
        }
    }
}

extern "C" void kernel_launch(void* const* d_in, const int* in_sizes, int n_in,
                              void* d_out, int out_size) {
    const float* x          = (const float*)d_in[0];
    const float* in_proj_w  = (const float*)d_in[1];
    const float* conv1d_w   = (const float*)d_in[2];
    const float* conv1d_b   = (const float*)d_in[3];
    const float* x_proj_w   = (const float*)d_in[4];
    const float* dt_proj_w  = (const float*)d_in[5];
    const float* dt_proj_b  = (const float*)d_in[6];
    // d_in[7] = A_log : unused (hs at depth 0 == BX at depth 0)
    const float* Dp         = (const float*)d_in[8];
    const float* out_proj_w = (const float*)d_in[9];
    const float* norm_w     = (const float*)d_in[10];
    float* out = (float*)d_out;

    float *xz = nullptr, *mid = nullptr, *wT = nullptr;
    cudaGetSymbolAddress((void**)&xz, g_xz);
    cudaGetSymbolAddress((void**)&mid, g_mid);
    cudaGetSymbolAddress((void**)&wT, g_wT);

    const int CONV_SMEM  = (144 * 56 + 144 + 216 * 68) * 4;          // 91584
    const int FUSED_SMEM = (1848 + 7448 + 96 * 196) * 4;             // 112448
    cudaFuncSetAttribute(conv_kernel,  cudaFuncAttributeMaxDynamicSharedMemorySize, CONV_SMEM);
    cudaFuncSetAttribute(fused_kernel, cudaFuncAttributeMaxDynamicSharedMemorySize, FUSED_SMEM);

    wt_kernel<<<dim3(27, 12, 2), dim3(32, 8)>>>(in_proj_w);

    // layer 0: input = x depth-0 slice (strided view)
    {
        long cs = 8L * NPOS, ns = 96L * 8L * NPOS;
        conv_kernel<<<dim3(6, 6, 8), 256, CONV_SMEM>>>(wT, x, cs, ns, norm_w, xz);
        fused_kernel<<<dim3(72, 2), 192, FUSED_SMEM>>>(
            conv1d_w, conv1d_b, x_proj_w, dt_proj_w, dt_proj_b, Dp, out_proj_w,
            x, cs, ns, mid);
    }
    // layer 1: input = mid (contiguous)
    {
        long cs = (long)NPOS, ns = 96L * NPOS;
        conv_kernel<<<dim3(6, 6, 8), 256, CONV_SMEM>>>(
            wT + 331776, mid, cs, ns, norm_w + 96, xz);
        fused_kernel<<<dim3(72, 2), 192, FUSED_SMEM>>>(
            conv1d_w + 768, conv1d_b + 192, x_proj_w + 7296, dt_proj_w + 1152,
            dt_proj_b + 192, Dp + 192, out_proj_w + 18432,
            mid, cs, ns, out);
    }
}